// round 17
// baseline (speedup 1.0000x reference)
#include <cuda_runtime.h>
#include <cuda_fp16.h>
#include <cstdint>

#define B_    16
#define T_    2048
#define D_    1024
#define DW    (D_ / 2)            // 512 uint32 words (fp16 pairs) per row
#define TT_   2046
#define MW_   682
#define M_    (B_ * MW_)          // 10912
#define MPAD  11008               // 86 * 128 = 172 * 64
#define NMUT  64
#define NBIN  32
#define NHEAD 96                  // 64 class + 32 binary (fused)
#define KSPLIT 2

// fp16 GEMM operands. Pairs (uint32 words) are stored permuted within each
// 16-pair (k32) group: pos(w) = (w&3)*4 + (w>>2). A thread's four needed
// pairs for two consecutive k16 MMA steps are then contiguous -> LDS.128.
__device__ __half g_wf[MPAD * D_];       // word features
__device__ __half g_h [MPAD * D_];       // tanh hidden
__device__ __half g_wt[D_ * D_];         // dense_w
__device__ __half g_hw[NHEAD * D_];      // fused head weights
__device__ float  g_hb[NHEAD];           // fused head bias (fp32)
__device__ float  g_part[KSPLIT * MPAD * NHEAD];  // head split-K partials
__device__ int    g_begin[M_];
__device__ int    g_cnt  [M_];

// ===========================================================================
// helpers
// ===========================================================================
__device__ __forceinline__ uint32_t smem_u32(const void* p) {
    return (uint32_t)__cvta_generic_to_shared(p);
}
__device__ __forceinline__ void cp16(uint32_t dst, const void* src) {
    asm volatile("cp.async.cg.shared.global [%0], [%1], 16;\n" :: "r"(dst), "l"(src));
}
#define CP_COMMIT() asm volatile("cp.async.commit_group;" ::: "memory")

__device__ __forceinline__ float tanh_fast(float x) {
    float y;
    asm("tanh.approx.f32 %0, %1;" : "=f"(y) : "f"(x));
    return y;
}
// pair index -> permuted position (16-pair groups)
__device__ __forceinline__ int ppos16(int pr) {
    return (pr & ~15) | ((pr & 3) << 2) | ((pr & 15) >> 2);
}
// fp16 m16n8k16, fp32 accumulate
__device__ __forceinline__ void mma16(float* c, const uint32_t* a,
                                      uint32_t b0, uint32_t b1) {
    asm volatile("mma.sync.aligned.m16n8k16.row.col.f32.f16.f16.f32 "
        "{%0,%1,%2,%3}, {%4,%5,%6,%7}, {%8,%9}, {%0,%1,%2,%3};"
        : "+f"(c[0]), "+f"(c[1]), "+f"(c[2]), "+f"(c[3])
        : "r"(a[0]), "r"(a[1]), "r"(a[2]), "r"(a[3]), "r"(b0), "r"(b1));
}

// ===========================================================================
// 1) per-batch scan of word_starts -> word begin token + token count
// ===========================================================================
__global__ void scan_kernel(const int* __restrict__ ws) {
    int b = blockIdx.x;
    const int* w = ws + b * TT_;
    __shared__ int partial[256];
    __shared__ int scnt[MW_];
    int tid = threadIdx.x;
    for (int i = tid; i < MW_; i += 256) scnt[i] = 0;

    int vals[8];
    int s = 0;
#pragma unroll
    for (int i = 0; i < 8; i++) {
        int t = tid * 8 + i;
        int v = (t < TT_) ? w[t] : 0;
        vals[i] = v; s += v;
    }
    partial[tid] = s;
    __syncthreads();
    for (int off = 1; off < 256; off <<= 1) {
        int v = partial[tid];
        int add = (tid >= off) ? partial[tid - off] : 0;
        __syncthreads();
        partial[tid] = v + add;
        __syncthreads();
    }
    int run = (tid > 0) ? partial[tid - 1] : 0;
#pragma unroll
    for (int i = 0; i < 8; i++) {
        int t = tid * 8 + i;
        if (t < TT_) {
            run += vals[i];
            int seg = run - 1;
            if (seg >= 0 && seg < MW_) {
                if (vals[i]) g_begin[b * MW_ + seg] = t;
                atomicAdd(&scnt[seg], 1);
            }
        }
    }
    __syncthreads();
    for (int i = tid; i < MW_; i += 256) g_cnt[b * MW_ + i] = scnt[i];
}

// ===========================================================================
// 2) word-feature segment sums -> fp16, quad-permuted
// ===========================================================================
__global__ void wf_kernel(const float* __restrict__ feat) {
    int m = blockIdx.x;
    int b = m / MW_;
    int tid = threadIdx.x;                       // float4 index 0..255
    int cnt = g_cnt[m];
    __half2* row = (__half2*)(g_wf + (size_t)m * D_);
    int pos0 = ppos16(2 * tid), pos1 = ppos16(2 * tid + 1);
    if (cnt == 0) {
        __half2 one = __float22half2_rn(make_float2(1.f, 1.f));
        row[pos0] = one; row[pos1] = one;
        return;
    }
    int t0 = g_begin[m];
    const float4* base = (const float4*)(feat + ((size_t)b * T_ + 1 + t0) * D_);
    float4 acc = base[tid];
    for (int i = 1; i < cnt; i++) {
        float4 v = base[(size_t)i * (D_ / 4) + tid];
        acc.x += v.x; acc.y += v.y; acc.z += v.z; acc.w += v.w;
    }
    row[pos0] = __float22half2_rn(make_float2(acc.x, acc.y));
    row[pos1] = __float22half2_rn(make_float2(acc.z, acc.w));
}

// ===========================================================================
// 2b) dense_w -> fp16, quad-permuted
// ===========================================================================
__global__ void roundw_kernel(const float* __restrict__ src) {
    int i = blockIdx.x * 256 + threadIdx.x;      // float4 index over D*D/4
    float4 v = ((const float4*)src)[i];
    __half2* dst = (__half2*)g_wt;
    dst[ppos16(2 * i)]     = __float22half2_rn(make_float2(v.x, v.y));
    dst[ppos16(2 * i + 1)] = __float22half2_rn(make_float2(v.z, v.w));
}

// ===========================================================================
// 3a) g_hw rows 0..63 = fp16(out_w) quad-permuted; g_hb[0..63] = out_b
// ===========================================================================
__global__ void headw_copy(const float* __restrict__ out_w, const float* __restrict__ out_b) {
    int i = blockIdx.x * 256 + threadIdx.x;      // float4 index over 64*1024/4
    float4 v = ((const float4*)out_w)[i];
    __half2* dst = (__half2*)g_hw;
    dst[ppos16(2 * i)]     = __float22half2_rn(make_float2(v.x, v.y));
    dst[ppos16(2 * i + 1)] = __float22half2_rn(make_float2(v.z, v.w));
    if (blockIdx.x == 0 && threadIdx.x < NMUT) g_hb[threadIdx.x] = out_b[threadIdx.x];
}

// ===========================================================================
// 3b) g_hw rows 64..95 = fp16(bin_w[:,64:] + bin_w[:,:64] @ out_w), permuted
//     grid (16, 4): block = 32 col-pairs x 8 rows
// ===========================================================================
__global__ void headw_bin(const float* __restrict__ out_w, const float* __restrict__ out_b,
                          const float* __restrict__ bin_w, const float* __restrict__ bin_b) {
    __shared__ float w1[8][NMUT];
    int tid = threadIdx.x;
    int rb  = blockIdx.y * 8;
    for (int i = tid; i < 8 * NMUT; i += 256) {
        int r = i >> 6, j = i & 63;
        w1[r][j] = bin_w[(size_t)(rb + r) * (D_ + NMUT) + j];
    }
    __syncthreads();

    int p  = tid & 31;
    int r  = tid >> 5;
    int pr = blockIdx.x * 32 + p;                // global pair 0..511
    int col = pr * 2;
    float a0 = bin_w[(size_t)(rb + r) * (D_ + NMUT) + NMUT + col];
    float a1 = bin_w[(size_t)(rb + r) * (D_ + NMUT) + NMUT + col + 1];
#pragma unroll 8
    for (int j = 0; j < NMUT; j++) {
        float2 v = *(const float2*)(out_w + (size_t)j * D_ + col);
        a0 += w1[r][j] * v.x;
        a1 += w1[r][j] * v.y;
    }
    __half2* dst = (__half2*)(g_hw + (size_t)(NMUT + rb + r) * D_);
    dst[ppos16(pr)] = __float22half2_rn(make_float2(a0, a1));

    if (blockIdx.x == 0 && blockIdx.y == 0 && tid < NBIN) {
        float bb = bin_b[tid];
        for (int j = 0; j < NMUT; j++)
            bb += bin_w[(size_t)tid * (D_ + NMUT) + j] * out_b[j];
        g_hb[NMUT + tid] = bb;
    }
}

// ===========================================================================
// 4) main fp16 GEMM: h = tanh(wf @ wt^T + b).  128x128 CTA tile, BK=64,
//    m16n8k16, 2-stage cp.async, 256 thr, 8 warps (4m x 2n), 32x64 warp tile.
//    Quad-permuted operands -> LDS.128 fragment loads (12 LDS per 32 HMMA).
//    SMEM row stride 48 words (==16 mod 32): conflict-free LDS.128 phases.
// ===========================================================================
__global__ __launch_bounds__(256) void tc_main(
    const __half* __restrict__ A, const __half* __restrict__ Bw,
    const float* __restrict__ bias, __half* __restrict__ O1)
{
    constexpr int RS  = 48;                      // smem row stride (words)
    constexpr int AST = 128 * RS;                // words per stage
    extern __shared__ uint32_t smem[];
    uint32_t* Asm = smem;                        // [2][128][48]
    uint32_t* Bsm = smem + 2 * AST;              // [2][128][48]

    const int tid = threadIdx.x;
    const int lane = tid & 31, wid = tid >> 5;
    const int g = lane >> 2, tg = lane & 3;
    const int wm = (wid & 3) * 32;
    const int wn = (wid >> 2) * 64;
    const int row0 = blockIdx.y * 128;
    const int col0 = blockIdx.x * 128;

    float acc[2][8][4];
#pragma unroll
    for (int i = 0; i < 2; i++)
#pragma unroll
        for (int j = 0; j < 8; j++)
#pragma unroll
            for (int q = 0; q < 4; q++) acc[i][j][q] = 0.f;

    const uint32_t* Ag = (const uint32_t*)A + (size_t)row0 * DW;
    const uint32_t* Bg = (const uint32_t*)Bw + (size_t)col0 * DW;

    auto loadStage = [&](int st, int kw0) {      // kw0 = word offset
        uint32_t* Ad = Asm + st * AST;
#pragma unroll
        for (int i = tid; i < 1024; i += 256) {
            int r = i >> 3, c = (i & 7) * 4;
            cp16(smem_u32(Ad + r * RS + c), Ag + (size_t)r * DW + kw0 + c);
        }
        uint32_t* Bd = Bsm + st * AST;
#pragma unroll
        for (int i = tid; i < 1024; i += 256) {
            int r = i >> 3, c = (i & 7) * 4;
            cp16(smem_u32(Bd + r * RS + c), Bg + (size_t)r * DW + kw0 + c);
        }
        CP_COMMIT();
    };
    auto compute = [&](int st) {
        const uint32_t* Ad = Asm + st * AST;
        const uint32_t* Bd = Bsm + st * AST;
#pragma unroll
        for (int dks = 0; dks < 2; dks++) {      // each dks = 2 k16 steps
            const int off = dks * 16 + tg * 4;   // quad position in row
            // A fragments for both k16 steps of this dks
            uint32_t a0[2][4], a1[2][4];
#pragma unroll
            for (int i = 0; i < 2; i++) {
                const uint32_t* ap = Ad + (wm + i * 16 + g) * RS + off;
                uint4 q0 = *(const uint4*)ap;            // row g
                uint4 q1 = *(const uint4*)(ap + 8 * RS); // row g+8
                a0[i][0] = q0.x; a0[i][1] = q1.x; a0[i][2] = q0.y; a0[i][3] = q1.y;
                a1[i][0] = q0.z; a1[i][1] = q1.z; a1[i][2] = q0.w; a1[i][3] = q1.w;
            }
#pragma unroll
            for (int j = 0; j < 8; j++) {
                const uint32_t* bp = Bd + (wn + j * 8 + g) * RS + off;
                uint4 bq = *(const uint4*)bp;
                mma16(acc[0][j], a0[0], bq.x, bq.y);
                mma16(acc[1][j], a0[1], bq.x, bq.y);
                mma16(acc[0][j], a1[0], bq.z, bq.w);
                mma16(acc[1][j], a1[1], bq.z, bq.w);
            }
        }
    };

    loadStage(0, 0);
    int st = 0;
    for (int kw = 0; kw < DW; kw += 32) {        // 16 chunks of 64 k
        asm volatile("cp.async.wait_group 0;" ::: "memory");
        __syncthreads();
        if (kw + 32 < DW) loadStage(st ^ 1, kw + 32);
        compute(st);
        st ^= 1;
    }

    // epilogue: bias + tanh.approx -> fp16 quad-permuted stores
#pragma unroll
    for (int i = 0; i < 2; i++) {
#pragma unroll
        for (int j = 0; j < 8; j++) {
            int r = row0 + wm + i * 16 + g;
            int c = col0 + wn + j * 8 + tg * 2;
            int pos = ppos16(c >> 1);
            __half2 x01 = __float22half2_rn(make_float2(
                tanh_fast(acc[i][j][0] + bias[c]),
                tanh_fast(acc[i][j][1] + bias[c + 1])));
            __half2 x23 = __float22half2_rn(make_float2(
                tanh_fast(acc[i][j][2] + bias[c]),
                tanh_fast(acc[i][j][3] + bias[c + 1])));
            ((__half2*)(O1 + (size_t)r * D_))[pos] = x01;
            ((__half2*)(O1 + (size_t)(r + 8) * D_))[pos] = x23;
        }
    }
}

// ===========================================================================
// 5) head GEMM split-K (fp16): partial[s] = h @ g_hw^T over 512-k slice s
//    grid (172, 2); BM=64, BN=96, BK=64 (8 chunks), fp32 partials out.
// ===========================================================================
__global__ __launch_bounds__(256) void tc_head(
    const __half* __restrict__ A, const __half* __restrict__ Bw)
{
    constexpr int RS  = 48;
    constexpr int AST = 64 * RS;
    constexpr int BST = 96 * RS;
    extern __shared__ uint32_t smem[];
    uint32_t* Asm = smem;                        // [2][64][48]
    uint32_t* Bsm = smem + 2 * AST;              // [2][96][48]

    const int tid = threadIdx.x;
    const int lane = tid & 31, wid = tid >> 5;
    const int g = lane >> 2, tg = lane & 3;
    const int wm = (wid & 1) * 32;
    const int wn = (wid >> 1) * 24;
    const int row0 = blockIdx.x * 64;
    const int kwbase = blockIdx.y * (DW / KSPLIT);   // 256-word k slice

    float acc[2][3][4];
#pragma unroll
    for (int i = 0; i < 2; i++)
#pragma unroll
        for (int j = 0; j < 3; j++)
#pragma unroll
            for (int q = 0; q < 4; q++) acc[i][j][q] = 0.f;

    const uint32_t* Ag = (const uint32_t*)A + (size_t)row0 * DW;
    const uint32_t* Bg = (const uint32_t*)Bw;

    auto loadStage = [&](int st, int kw0) {
        uint32_t* Ad = Asm + st * AST;
#pragma unroll
        for (int i = tid; i < 512; i += 256) {
            int r = i >> 3, c = (i & 7) * 4;
            cp16(smem_u32(Ad + r * RS + c), Ag + (size_t)r * DW + kw0 + c);
        }
        uint32_t* Bd = Bsm + st * BST;
#pragma unroll
        for (int i = tid; i < 768; i += 256) {
            int r = i >> 3, c = (i & 7) * 4;
            cp16(smem_u32(Bd + r * RS + c), Bg + (size_t)r * DW + kw0 + c);
        }
        CP_COMMIT();
    };
    auto compute = [&](int st) {
        const uint32_t* Ad = Asm + st * AST;
        const uint32_t* Bd = Bsm + st * BST;
#pragma unroll
        for (int dks = 0; dks < 2; dks++) {
            const int off = dks * 16 + tg * 4;
            uint32_t a0[2][4], a1[2][4];
#pragma unroll
            for (int i = 0; i < 2; i++) {
                const uint32_t* ap = Ad + (wm + i * 16 + g) * RS + off;
                uint4 q0 = *(const uint4*)ap;
                uint4 q1 = *(const uint4*)(ap + 8 * RS);
                a0[i][0] = q0.x; a0[i][1] = q1.x; a0[i][2] = q0.y; a0[i][3] = q1.y;
                a1[i][0] = q0.z; a1[i][1] = q1.z; a1[i][2] = q0.w; a1[i][3] = q1.w;
            }
#pragma unroll
            for (int j = 0; j < 3; j++) {
                const uint32_t* bp = Bd + (wn + j * 8 + g) * RS + off;
                uint4 bq = *(const uint4*)bp;
                mma16(acc[0][j], a0[0], bq.x, bq.y);
                mma16(acc[1][j], a0[1], bq.x, bq.y);
                mma16(acc[0][j], a1[0], bq.z, bq.w);
                mma16(acc[1][j], a1[1], bq.z, bq.w);
            }
        }
    };

    loadStage(0, kwbase);
    int st = 0;
    for (int kw = 0; kw < DW / KSPLIT; kw += 32) {   // 8 chunks
        asm volatile("cp.async.wait_group 0;" ::: "memory");
        __syncthreads();
        if (kw + 32 < DW / KSPLIT) loadStage(st ^ 1, kwbase + kw + 32);
        compute(st);
        st ^= 1;
    }

    float* P = g_part + (size_t)blockIdx.y * MPAD * NHEAD;
#pragma unroll
    for (int i = 0; i < 2; i++) {
#pragma unroll
        for (int j = 0; j < 3; j++) {
            int c = wn + j * 8 + tg * 2;
#pragma unroll
            for (int rr = 0; rr < 2; rr++) {
                int row = row0 + wm + i * 16 + g + rr * 8;
                float2 v;
                v.x = acc[i][j][rr * 2 + 0];
                v.y = acc[i][j][rr * 2 + 1];
                *(float2*)(P + (size_t)row * NHEAD + c) = v;
            }
        }
    }
}

// ===========================================================================
// 6) reduce split-K partials + bias -> wcl / bin (float4 path)
// ===========================================================================
__global__ void reduce_head(float* __restrict__ wcl, float* __restrict__ bin) {
    int i = blockIdx.x * 256 + threadIdx.x;      // 4-col group index
    if (i >= M_ * (NHEAD / 4)) return;
    int r = i / (NHEAD / 4), cg = i - r * (NHEAD / 4);
    int c = cg * 4;
    float4 s = *(const float4*)(g_hb + c);
#pragma unroll
    for (int p = 0; p < KSPLIT; p++) {
        float4 v = *(const float4*)(g_part + (size_t)p * MPAD * NHEAD + (size_t)r * NHEAD + c);
        s.x += v.x; s.y += v.y; s.z += v.z; s.w += v.w;
    }
    if (c < NMUT) *(float4*)(wcl + (size_t)r * NMUT + c) = s;
    else          *(float4*)(bin + (size_t)r * NBIN + (c - NMUT)) = s;
}

// ===========================================================================
extern "C" void kernel_launch(void* const* d_in, const int* in_sizes, int n_in,
                              void* d_out, int out_size)
{
    const float* features = (const float*)d_in[0];
    const int*   wstarts  = (const int*)d_in[1];
    const float* dense_w  = (const float*)d_in[2];
    const float* dense_b  = (const float*)d_in[3];
    const float* out_w    = (const float*)d_in[4];
    const float* out_b    = (const float*)d_in[5];
    const float* bin_w    = (const float*)d_in[6];
    const float* bin_b    = (const float*)d_in[7];
    (void)in_sizes; (void)n_in; (void)out_size;

    __half *wf, *h, *wt, *hw;
    cudaGetSymbolAddress((void**)&wf, g_wf);
    cudaGetSymbolAddress((void**)&h,  g_h);
    cudaGetSymbolAddress((void**)&wt, g_wt);
    cudaGetSymbolAddress((void**)&hw, g_hw);

    float* wcl = (float*)d_out;                        // [M, 64]
    float* bin = (float*)d_out + (size_t)M_ * NMUT;    // [M, 32]

    const int SMEM_MAIN = 2 * (128 * 48 + 128 * 48) * 4;   // 98304 B
    const int SMEM_HEAD = 2 * (64 * 48 + 96 * 48) * 4;     // 61440 B
    cudaFuncSetAttribute(tc_main, cudaFuncAttributeMaxDynamicSharedMemorySize, SMEM_MAIN);
    cudaFuncSetAttribute(tc_head, cudaFuncAttributeMaxDynamicSharedMemorySize, SMEM_HEAD);

    // one-time side stream + fork/join events (created outside capture)
    static cudaStream_t s_side = nullptr;
    static cudaEvent_t ev_fork = nullptr, ev_w = nullptr, ev_join = nullptr;
    if (s_side == nullptr) {
        cudaStreamCreateWithFlags(&s_side, cudaStreamNonBlocking);
        cudaEventCreateWithFlags(&ev_fork, cudaEventDisableTiming);
        cudaEventCreateWithFlags(&ev_w,    cudaEventDisableTiming);
        cudaEventCreateWithFlags(&ev_join, cudaEventDisableTiming);
    }

    cudaEventRecord(ev_fork, 0);
    // main: scan(1), wf(2)
    scan_kernel<<<B_, 256>>>(wstarts);
    wf_kernel<<<M_, 256>>>(features);
    // side: roundw — concurrent with scan+wf
    cudaStreamWaitEvent(s_side, ev_fork, 0);
    roundw_kernel<<<D_ * D_ / 4 / 256, 256, 0, s_side>>>(dense_w);
    cudaEventRecord(ev_w, s_side);
    // main: tc_main — needs wf (stream order) + roundw (event)
    cudaStreamWaitEvent(0, ev_w, 0);
    tc_main<<<dim3(8, MPAD / 128), 256, SMEM_MAIN>>>(wf, wt, dense_b, h);
    // side: head-weight prep — concurrent with tc_main
    headw_copy<<<NMUT * D_ / 4 / 256, 256, 0, s_side>>>(out_w, out_b);
    headw_bin<<<dim3(16, 4), 256, 0, s_side>>>(out_w, out_b, bin_w, bin_b);
    cudaEventRecord(ev_join, s_side);
    // join, then heads
    cudaStreamWaitEvent(0, ev_join, 0);
    tc_head<<<dim3(MPAD / 64, KSPLIT), 256, SMEM_HEAD>>>(h, hw);
    reduce_head<<<(M_ * (NHEAD / 4) + 255) / 256, 256>>>(wcl, bin);
}